// round 5
// baseline (speedup 1.0000x reference)
#include <cuda_runtime.h>
#include <math.h>

#define NNODES 50000
#define NEDGES 1600000
#define ETOT   (NEDGES + NNODES)
#define INCH   64
#define HEADS  8
#define HID    16
#define HH     (HEADS*HID)   /* 128 */
#define NGRAPH 256
#define OUTC   32
#define CAP    128                         /* bucket capacity per node */
#define GG     ((NNODES + 31) / 32)        /* gemm1 blocks = 1563 */
#define GH     ((ETOT + 255) / 256)        /* fill blocks  = 6446 */

// ---------------- scratch ----------------
__device__ __align__(16) float g_xl1[NNODES*HH];
__device__ __align__(16) float g_xr1[NNODES*HH];
__device__ __align__(16) float g_out1[NNODES*HH];
__device__ __align__(16) float g_xl2[NNODES*HID];
__device__ __align__(16) float g_xr2[NNODES*HID];
__device__ __align__(16) float g_pool[NGRAPH*HID];
__device__ __align__(16) float g_cnt[NGRAPH];
__device__ int g_count[NNODES];
__device__ int g_slot[(size_t)NNODES * CAP];

__device__ __forceinline__ float elu1f(float v) { return v > 0.f ? v : expm1f(v); }
__device__ __forceinline__ float lrelu(float v) { return fmaxf(v, 0.2f * v); }

// ---------------- zero: count + pool + cnt ----------------
__global__ void zero_kernel() {
    int i = blockIdx.x * blockDim.x + threadIdx.x;
    if (i < NNODES) g_count[i] = 0;
    if (i < NGRAPH * HID) g_pool[i] = 0.f;
    if (i < NGRAPH) g_cnt[i] = 0.f;
}

// ---------------- fused: gemm1 (first GG blocks) || bucket-fill (rest) ----------------
__global__ void __launch_bounds__(256) fusedA_kernel(
        const float* __restrict__ x,
        const float* __restrict__ wl, const float* __restrict__ bl,
        const float* __restrict__ wr, const float* __restrict__ br,
        const int* __restrict__ src, const int* __restrict__ dst) {
    if (blockIdx.x >= GG) {
        // ---- direct bucket fill: hist + fill in ONE pass, no scan needed ----
        int e = (blockIdx.x - GG) * 256 + threadIdx.x;
        if (e < ETOT) {
            int s, d;
            if (e < NEDGES) { s = src[e]; d = dst[e]; } else { s = e - NEDGES; d = s; }
            int pos = atomicAdd(&g_count[d], 1);
            if (pos < CAP) g_slot[(size_t)d * CAP + pos] = s;
        }
        return;
    }
    // ---- gemm1: xl1 = x@wl1+bl1, xr1 = x@wr1+br1 ----
    __shared__ __align__(16) float xs[8][INCH];
    int tid = threadIdx.x;
    int c = tid & (HH - 1);
    const float* w = (tid < HH) ? wl : wr;
    float bias = (tid < HH) ? bl[c] : br[c];
    float wreg[INCH];
    #pragma unroll
    for (int k = 0; k < INCH; k++) wreg[k] = __ldg(&w[k * HH + c]);
    float* outp = (tid < HH) ? g_xl1 : g_xr1;
    int node0 = blockIdx.x * 32;
    for (int base = 0; base < 32; base += 8) {
        int n0 = node0 + base;
        __syncthreads();
        if (tid < 128) {
            int nn = tid >> 4, k4 = tid & 15;
            int g = n0 + nn;
            float4 v = (g < NNODES) ? ((const float4*)(x + (size_t)g * INCH))[k4]
                                    : make_float4(0.f, 0.f, 0.f, 0.f);
            ((float4*)&xs[nn][0])[k4] = v;
        }
        __syncthreads();
        float acc[8];
        #pragma unroll
        for (int j = 0; j < 8; j++) acc[j] = bias;
        #pragma unroll
        for (int k4 = 0; k4 < 16; k4++) {
            #pragma unroll
            for (int j = 0; j < 8; j++) {
                float4 xv = ((const float4*)&xs[j][0])[k4];
                acc[j] = fmaf(xv.x, wreg[4 * k4 + 0],
                         fmaf(xv.y, wreg[4 * k4 + 1],
                         fmaf(xv.z, wreg[4 * k4 + 2],
                         fmaf(xv.w, wreg[4 * k4 + 3], acc[j]))));
            }
        }
        #pragma unroll
        for (int j = 0; j < 8; j++) {
            int g = n0 + j;
            if (g < NNODES) outp[(size_t)g * HH + c] = acc[j];
        }
    }
}

// ---------------- conv1 fused edge pass ----------------
// One warp per dst. 32 indices loaded cooperatively (1 coalesced LDG / 32 edges),
// broadcast via shfl -> gather pipeline is 4-deep with no idx latency in the chain.
__device__ __forceinline__ float edge1_exp(float4 xv, float4 xr, float4 aw) {
    float p = lrelu(xv.x + xr.x) * aw.x + lrelu(xv.y + xr.y) * aw.y
            + lrelu(xv.z + xr.z) * aw.z + lrelu(xv.w + xr.w) * aw.w;
    p += __shfl_xor_sync(0xffffffffu, p, 1);
    p += __shfl_xor_sync(0xffffffffu, p, 2);
    return __expf(p);
}

__global__ void __launch_bounds__(256) edge1_fused_kernel(const float* __restrict__ att,
                                                          const float* __restrict__ bias) {
    int warp = (blockIdx.x * blockDim.x + threadIdx.x) >> 5;
    if (warp >= NNODES) return;
    int lane = threadIdx.x & 31;
    int d = warp;
    float4 xr = ((const float4*)(g_xr1 + (size_t)d * HH))[lane];
    float4 aw = __ldg(&((const float4*)att)[lane]);
    float4 acc = make_float4(0.f, 0.f, 0.f, 0.f);
    float den = 0.f;
    int deg = min(g_count[d], CAP);
    const int* slot = g_slot + (size_t)d * CAP;
    for (int blk = 0; blk < deg; blk += 32) {
        int nn = min(32, deg - blk);                  // warp-uniform
        int myidx = (lane < nn) ? slot[blk + lane] : 0;
        int j = 0;
        for (; j + 3 < nn; j += 4) {
            int s0 = __shfl_sync(0xffffffffu, myidx, j);
            int s1 = __shfl_sync(0xffffffffu, myidx, j + 1);
            int s2 = __shfl_sync(0xffffffffu, myidx, j + 2);
            int s3 = __shfl_sync(0xffffffffu, myidx, j + 3);
            float4 x0 = ((const float4*)(g_xl1 + (size_t)s0 * HH))[lane];
            float4 x1 = ((const float4*)(g_xl1 + (size_t)s1 * HH))[lane];
            float4 x2 = ((const float4*)(g_xl1 + (size_t)s2 * HH))[lane];
            float4 x3 = ((const float4*)(g_xl1 + (size_t)s3 * HH))[lane];
            float e0 = edge1_exp(x0, xr, aw);
            float e1 = edge1_exp(x1, xr, aw);
            float e2 = edge1_exp(x2, xr, aw);
            float e3 = edge1_exp(x3, xr, aw);
            acc.x += e0 * x0.x + e1 * x1.x + e2 * x2.x + e3 * x3.x;
            acc.y += e0 * x0.y + e1 * x1.y + e2 * x2.y + e3 * x3.y;
            acc.z += e0 * x0.z + e1 * x1.z + e2 * x2.z + e3 * x3.z;
            acc.w += e0 * x0.w + e1 * x1.w + e2 * x2.w + e3 * x3.w;
            den += (e0 + e1) + (e2 + e3);
        }
        for (; j < nn; j++) {
            int s0 = __shfl_sync(0xffffffffu, myidx, j);
            float4 x0 = ((const float4*)(g_xl1 + (size_t)s0 * HH))[lane];
            float e0 = edge1_exp(x0, xr, aw);
            acc.x += e0 * x0.x; acc.y += e0 * x0.y; acc.z += e0 * x0.z; acc.w += e0 * x0.w;
            den += e0;
        }
    }
    float inv = 1.f / (den + 1e-16f);
    float4 b = __ldg(&((const float4*)bias)[lane]);
    float4 o;
    o.x = elu1f(fmaf(acc.x, inv, b.x));
    o.y = elu1f(fmaf(acc.y, inv, b.y));
    o.z = elu1f(fmaf(acc.z, inv, b.z));
    o.w = elu1f(fmaf(acc.w, inv, b.w));
    ((float4*)(g_out1 + (size_t)d * HH))[lane] = o;
}

// ---------------- conv2 node transforms ----------------
__global__ void __launch_bounds__(256) gemm2_kernel(
        const float* __restrict__ wl, const float* __restrict__ bl,
        const float* __restrict__ wr, const float* __restrict__ br) {
    __shared__ float ws[HH][32];
    __shared__ float bs[32];
    __shared__ __align__(16) float xs[8][HH];
    int tid = threadIdx.x;
    for (int i = tid; i < HH * 32; i += 256) {
        int k = i >> 5, cc = i & 31;
        ws[k][cc] = (cc < HID) ? wl[k * HID + cc] : wr[k * HID + (cc - HID)];
    }
    if (tid < 32) bs[tid] = (tid < HID) ? bl[tid] : br[tid - HID];
    int col = tid & 31;
    int ln = tid >> 5;
    int node0 = blockIdx.x * 32;
    for (int base = 0; base < 32; base += 8) {
        int n0 = node0 + base;
        __syncthreads();
        {
            int nn = tid >> 5, k4 = tid & 31;
            int g = n0 + nn;
            float4 v = (g < NNODES) ? ((const float4*)(g_out1 + (size_t)g * HH))[k4]
                                    : make_float4(0.f, 0.f, 0.f, 0.f);
            ((float4*)&xs[nn][0])[k4] = v;
        }
        __syncthreads();
        int g = n0 + ln;
        float acc = bs[col];
        #pragma unroll
        for (int k4 = 0; k4 < 32; k4++) {
            float4 xv = ((const float4*)&xs[ln][0])[k4];
            acc = fmaf(xv.x, ws[4 * k4 + 0][col],
                  fmaf(xv.y, ws[4 * k4 + 1][col],
                  fmaf(xv.z, ws[4 * k4 + 2][col],
                  fmaf(xv.w, ws[4 * k4 + 3][col], acc))));
        }
        if (g < NNODES) {
            if (col < HID) g_xl2[(size_t)g * HID + col] = acc;
            else           g_xr2[(size_t)g * HID + (col - HID)] = acc;
        }
    }
}

// ---------------- conv2 fused edge pass + bias2 + ELU + mean-pool ----------------
// Half-warps process alternating edges; all loops warp-uniform; odd-tail edge is
// computed by both halves with sub==1 masked via predicate (no divergent shfl).
__global__ void __launch_bounds__(256) edge2_fused_kernel(const float* __restrict__ att,
                                                          const float* __restrict__ bias,
                                                          const int* __restrict__ batch) {
    int warp = (blockIdx.x * blockDim.x + threadIdx.x) >> 5;
    if (warp >= NNODES) return;
    int lane = threadIdx.x & 31;
    int c = lane & 15;
    int sub = lane >> 4;
    int d = warp;
    float xr = g_xr2[(size_t)d * HID + c];
    float aw = __ldg(&att[c]);
    float acc = 0.f, den = 0.f;
    int deg = min(g_count[d], CAP);
    const int* slot = g_slot + (size_t)d * CAP;
    for (int blk = 0; blk < deg; blk += 32) {
        int nn = min(32, deg - blk);                  // warp-uniform
        int myidx = (lane < nn) ? slot[blk + lane] : 0;
        int j = 0;
        for (; j + 3 < nn; j += 4) {                  // 4 edges per iter (2 per half)
            int s0 = __shfl_sync(0xffffffffu, myidx, j + sub);
            int s1 = __shfl_sync(0xffffffffu, myidx, j + 2 + sub);
            float xl0 = g_xl2[(size_t)s0 * HID + c];
            float xl1 = g_xl2[(size_t)s1 * HID + c];
            float p0 = lrelu(xl0 + xr) * aw;
            float p1 = lrelu(xl1 + xr) * aw;
            p0 += __shfl_xor_sync(0xffffffffu, p0, 1);
            p1 += __shfl_xor_sync(0xffffffffu, p1, 1);
            p0 += __shfl_xor_sync(0xffffffffu, p0, 2);
            p1 += __shfl_xor_sync(0xffffffffu, p1, 2);
            p0 += __shfl_xor_sync(0xffffffffu, p0, 4);
            p1 += __shfl_xor_sync(0xffffffffu, p1, 4);
            p0 += __shfl_xor_sync(0xffffffffu, p0, 8);
            p1 += __shfl_xor_sync(0xffffffffu, p1, 8);
            float e0 = __expf(p0), e1 = __expf(p1);
            acc += e0 * xl0 + e1 * xl1;
            den += e0 + e1;
        }
        for (; j < nn; j += 2) {                      // 2-edge / 1-edge tail, uniform
            int take1 = (j + 1 < nn);
            int idx = j + (take1 ? sub : 0);          // if only 1 left, both halves same edge
            int s = __shfl_sync(0xffffffffu, myidx, idx);
            float xl = g_xl2[(size_t)s * HID + c];
            float p = lrelu(xl + xr) * aw;
            p += __shfl_xor_sync(0xffffffffu, p, 1);
            p += __shfl_xor_sync(0xffffffffu, p, 2);
            p += __shfl_xor_sync(0xffffffffu, p, 4);
            p += __shfl_xor_sync(0xffffffffu, p, 8);
            bool ok = take1 || (sub == 0);
            float ex = ok ? __expf(p) : 0.f;
            acc += ex * xl;
            den += ex;
        }
    }
    acc += __shfl_xor_sync(0xffffffffu, acc, 16);
    den += __shfl_xor_sync(0xffffffffu, den, 16);
    if (sub == 0) {
        float o = elu1f(acc / (den + 1e-16f) + __ldg(&bias[c]));
        int b = batch[d];
        atomicAdd(&g_pool[b * HID + c], o);
        if (c == 0) atomicAdd(&g_cnt[b], 1.f);
    }
}

// ---------------- final MLP ----------------
__global__ void mlp_kernel(const float* __restrict__ w1, const float* __restrict__ b1,
                           const float* __restrict__ w2, const float* __restrict__ b2,
                           const float* __restrict__ w3, const float* __restrict__ b3,
                           float* __restrict__ out) {
    __shared__ float s1[HID * 32], sb1[32];
    __shared__ float s2[32 * HID], sb2[HID];
    __shared__ float s3[HID * 32], sb3[32];
    int tid = threadIdx.x;
    for (int i = tid; i < HID * 32; i += 256) s1[i] = w1[i];
    for (int i = tid; i < 32 * HID; i += 256) s2[i] = w2[i];
    for (int i = tid; i < HID * 32; i += 256) s3[i] = w3[i];
    if (tid < 32) { sb1[tid] = b1[tid]; sb3[tid] = b3[tid]; }
    if (tid < HID) sb2[tid] = b2[tid];
    __syncthreads();
    int b = tid;
    float cnt = fmaxf(g_cnt[b], 1.f);
    float h[HID];
    #pragma unroll
    for (int c = 0; c < HID; c++) h[c] = g_pool[b * HID + c] / cnt;
    float t1[32];
    #pragma unroll
    for (int j = 0; j < 32; j++) {
        float s = sb1[j];
        #pragma unroll
        for (int k = 0; k < HID; k++) s += h[k] * s1[k * 32 + j];
        t1[j] = elu1f(s);
    }
    float t2[HID];
    #pragma unroll
    for (int j = 0; j < HID; j++) {
        float s = sb2[j];
        #pragma unroll
        for (int k = 0; k < 32; k++) s += t1[k] * s2[k * HID + j];
        t2[j] = elu1f(s);
    }
    #pragma unroll
    for (int j = 0; j < 32; j++) {
        float s = sb3[j];
        #pragma unroll
        for (int k = 0; k < HID; k++) s += t2[k] * s3[k * 32 + j];
        out[b * 32 + j] = s;
    }
}

// ---------------- launch ----------------
extern "C" void kernel_launch(void* const* d_in, const int* in_sizes, int n_in,
                              void* d_out, int out_size) {
    const float* x     = (const float*)d_in[0];
    const int*   ei    = (const int*)  d_in[1];
    const int*   batch = (const int*)  d_in[2];
    const float* wl1   = (const float*)d_in[3];
    const float* bl1   = (const float*)d_in[4];
    const float* wr1   = (const float*)d_in[5];
    const float* br1   = (const float*)d_in[6];
    const float* att1  = (const float*)d_in[7];
    const float* bias1 = (const float*)d_in[8];
    const float* wl2   = (const float*)d_in[9];
    const float* bl2   = (const float*)d_in[10];
    const float* wr2   = (const float*)d_in[11];
    const float* br2   = (const float*)d_in[12];
    const float* att2  = (const float*)d_in[13];
    const float* bias2 = (const float*)d_in[14];
    const float* wm1   = (const float*)d_in[15];
    const float* bm1   = (const float*)d_in[16];
    const float* wm2   = (const float*)d_in[17];
    const float* bm2   = (const float*)d_in[18];
    const float* wm3   = (const float*)d_in[19];
    const float* bm3   = (const float*)d_in[20];
    const int* src = ei;
    const int* dst = ei + NEDGES;
    float* out = (float*)d_out;

    zero_kernel<<<(NNODES + 511) / 512, 512>>>();
    fusedA_kernel<<<GG + GH, 256>>>(x, wl1, bl1, wr1, br1, src, dst);
    edge1_fused_kernel<<<(NNODES * 32 + 255) / 256, 256>>>(att1, bias1);
    gemm2_kernel<<<(NNODES + 31) / 32, 256>>>(wl2, bl2, wr2, br2);
    edge2_fused_kernel<<<(NNODES * 32 + 255) / 256, 256>>>(att2, bias2, batch);
    mlp_kernel<<<1, 256>>>(wm1, bm1, wm2, bm2, wm3, bm3, out);
}